// round 6
// baseline (speedup 1.0000x reference)
#include <cuda_runtime.h>
#include <cuda_bf16.h>
#include <math.h>
#include <stdint.h>

// ---------------------------------------------------------------------------
// DeepseekV2 MLA forward, B=1 S=2048 HID=2048 H=16 NOPE=128 ROPE=64 VD=128.
// Round 6: tcgen05 unavailable (harness compiles -arch=sm_100, ptxas rejects
// it). Optimized mma.sync engine instead: 2 CTAs/SM (2-stage pipeline,
// smem 80KB, __launch_bounds__(256,2) reg cap), single BN=128 template,
// B-fragments loaded per-group to cut register pressure.
// Operands pre-split bf16 hi/lo; 3-pass compensated accumulation.
// ---------------------------------------------------------------------------

#define S_LEN 2048
#define HID   2048
#define HEADS 16
#define NOPE  128
#define ROPE  64
#define VD    128
#define QD    192
#define QLR   1536
#define KVLR  512
#define KVD_W (KVLR + 64)            // 576
#define QUP_N (HEADS * QD)           // 3072
#define KUP_N (HEADS * (NOPE + VD))  // 4096
#define WKD_PAD 640                  // Wkv_down rows padded to 5*128

// ---------------- fp32 scratch ----------------
#define F_QRAW 0L
#define F_QBUF (F_QRAW + (long)S_LEN * QLR)
#define F_KVD  (F_QBUF + (long)S_LEN * QUP_N)
#define F_KV   (F_KVD  + (long)S_LEN * KVD_W)
#define F_CTX  (F_KV   + (long)S_LEN * KUP_N)
#define F_TOT  (F_CTX  + (long)S_LEN * HID)

// ---------------- bf16 hi/lo scratch ----------------
#define O_HID  0L
#define O_WQD  (O_HID  + (long)S_LEN * HID)
#define O_WQU  (O_WQD  + (long)QLR * HID)
#define O_WKD  (O_WQU  + (long)QUP_N * QLR)
#define O_WKU  (O_WKD  + (long)WKD_PAD * HID)   // pad rows: never written,
#define O_WO   (O_WKU  + (long)KUP_N * KVLR)    // never stored (Nvalid guard)
#define O_QRN  (O_WO   + (long)HID * (HEADS * VD))
#define O_KVN  (O_QRN  + (long)S_LEN * QLR)
#define O_QALL (O_KVN  + (long)S_LEN * KVLR)
#define O_KALL (O_QALL + (long)HEADS * S_LEN * QD)
#define O_VT   (O_KALL + (long)HEADS * S_LEN * QD)
#define O_ATTN (O_VT   + (long)HEADS * VD * S_LEN)
#define O_CTX  (O_ATTN + (long)HEADS * S_LEN * S_LEN)
#define O_TOT  (O_CTX  + (long)S_LEN * HID)

__device__ __align__(256) float         g_f32[F_TOT];
__device__ __align__(256) __nv_bfloat16 g_hi[O_TOT];
__device__ __align__(256) __nv_bfloat16 g_lo[O_TOT];

// ---------------------------------------------------------------------------
__device__ __forceinline__ unsigned smem_u32(const void* p) {
    return (unsigned)__cvta_generic_to_shared(p);
}
__device__ __forceinline__ void ldm_x4(uint32_t r[4], unsigned addr) {
    asm volatile("ldmatrix.sync.aligned.m8n8.x4.shared.b16 {%0,%1,%2,%3}, [%4];"
                 : "=r"(r[0]), "=r"(r[1]), "=r"(r[2]), "=r"(r[3]) : "r"(addr));
}
__device__ __forceinline__ void mma16816(float d[4], const uint32_t a[4],
                                         const uint32_t b0, const uint32_t b1) {
    asm volatile(
        "mma.sync.aligned.m16n8k16.row.col.f32.bf16.bf16.f32 "
        "{%0,%1,%2,%3}, {%4,%5,%6,%7}, {%8,%9}, {%0,%1,%2,%3};"
        : "+f"(d[0]), "+f"(d[1]), "+f"(d[2]), "+f"(d[3])
        : "r"(a[0]), "r"(a[1]), "r"(a[2]), "r"(a[3]), "r"(b0), "r"(b1));
}
__device__ __forceinline__ void cp16(unsigned dst, const void* src) {
    asm volatile("cp.async.cg.shared.global [%0], [%1], 16;"
                 :: "r"(dst), "l"(src));
}
#define CP_COMMIT() asm volatile("cp.async.commit_group;" ::: "memory")
#define CP_WAIT1()  asm volatile("cp.async.wait_group 1;" ::: "memory")

__device__ __forceinline__ void split1(float v, __nv_bfloat16* h,
                                       __nv_bfloat16* l) {
    __nv_bfloat16 a = __float2bfloat16(v);
    *h = a;
    *l = __float2bfloat16(v - __bfloat162float(a));
}

// ---------------------------------------------------------------------------
// elementwise fp32 -> bf16 hi/lo split
// ---------------------------------------------------------------------------
__global__ void split_hl(const float* __restrict__ x,
                         __nv_bfloat16* __restrict__ h,
                         __nv_bfloat16* __restrict__ l, long n)
{
    long i = ((long)blockIdx.x * 256 + threadIdx.x) * 4;
    if (i >= n) return;
    float4 v = *(const float4*)(x + i);
    __nv_bfloat162 h01 = __floats2bfloat162_rn(v.x, v.y);
    __nv_bfloat162 h23 = __floats2bfloat162_rn(v.z, v.w);
    __nv_bfloat162 l01 = __floats2bfloat162_rn(v.x - __low2float(h01),
                                               v.y - __high2float(h01));
    __nv_bfloat162 l23 = __floats2bfloat162_rn(v.z - __low2float(h23),
                                               v.w - __high2float(h23));
    uint2 uh, ul;
    uh.x = *(uint32_t*)&h01; uh.y = *(uint32_t*)&h23;
    ul.x = *(uint32_t*)&l01; ul.y = *(uint32_t*)&l23;
    *(uint2*)(h + i) = uh;
    *(uint2*)(l + i) = ul;
}

// ---------------------------------------------------------------------------
// Tensor-core GEMM (mma.sync): C[M,N] = scale*(A[M,K] @ B[N,K]^T) + bias.
// BM=128, BN=128, BK=32, 256 threads (8 warps: 4m x 2n, warp tile 32x64).
// 2-stage cp.async pipeline, 2 CTAs/SM. Optional bf16 hi/lo C output.
// ---------------------------------------------------------------------------
#define SST 40                        // smem row stride, bf16 elems (80 B)
#define STG 2
#define STAGE_B 40960u                // (128+128 rows hi+lo) * 80 B
#define A_LOB   10240u
#define B_HIB   20480u
#define B_LOB   30720u

template<bool CSKIP, bool CKLIM>
__global__ __launch_bounds__(256, 2)
void gemm_hl(const __nv_bfloat16* __restrict__ Agh,
             const __nv_bfloat16* __restrict__ Agl, long sA,
             const __nv_bfloat16* __restrict__ Bgh,
             const __nv_bfloat16* __restrict__ Bgl, long sB,
             float* __restrict__ C, long sC,
             __nv_bfloat16* __restrict__ Ch, __nv_bfloat16* __restrict__ Cl,
             int K, int lda, int ldb, int ldc, int Nvalid,
             const float* __restrict__ bias, float scale)
{
    extern __shared__ __nv_bfloat16 sm[];

    const int bz = blockIdx.z;
    Agh += (long)bz * sA;  Agl += (long)bz * sA;
    Bgh += (long)bz * sB;  Bgl += (long)bz * sB;
    C   += (long)bz * sC;
    if (Ch) { Ch += (long)bz * sC; Cl += (long)bz * sC; }

    const int row0 = blockIdx.y * 128;
    const int col0 = blockIdx.x * 128;
    if (CSKIP && col0 >= row0 + 128) return;

    const int kEnd = CKLIM ? min(K, row0 + 128) : K;
    const int nc = kEnd >> 5;

    const int tid = threadIdx.x;
    const int wid = tid >> 5, lane = tid & 31;
    const int wm = wid & 3, wn = wid >> 2;

    // global load geometry: row tid/2, two 16B chunks at (tid&1)*32B
    const int gr  = tid >> 1;
    const int gcb = (tid & 1) * 16;                  // bf16 elems (32 B)
    const __nv_bfloat16* pAh = Agh + (long)(row0 + gr) * lda + gcb;
    const __nv_bfloat16* pAl = Agl + (long)(row0 + gr) * lda + gcb;
    const __nv_bfloat16* pBh = Bgh + (long)(col0 + gr) * ldb + gcb;
    const __nv_bfloat16* pBl = Bgl + (long)(col0 + gr) * ldb + gcb;

    const unsigned smb = smem_u32(sm);
    const unsigned soff = (unsigned)(gr * SST + gcb) * 2;  // bytes in-buffer

    float acc[2][8][4];
#pragma unroll
    for (int i = 0; i < 2; i++)
#pragma unroll
        for (int j = 0; j < 8; j++)
#pragma unroll
            for (int k = 0; k < 4; k++) acc[i][j][k] = 0.f;

    auto load_stage = [&](int kc, int slot) {
        const int k0 = kc << 5;
        const unsigned so = smb + (unsigned)slot * STAGE_B + soff;
        cp16(so,                  pAh + k0);
        cp16(so + 16,             pAh + k0 + 8);
        cp16(so + A_LOB,          pAl + k0);
        cp16(so + A_LOB + 16,     pAl + k0 + 8);
        cp16(so + B_HIB,          pBh + k0);
        cp16(so + B_HIB + 16,     pBh + k0 + 8);
        cp16(so + B_LOB,          pBl + k0);
        cp16(so + B_LOB + 16,     pBl + k0 + 8);
    };

    load_stage(0, 0);
    CP_COMMIT();

    // ldmatrix per-thread offsets
    const int a_ri = lane & 15;
    const int a_k8 = (lane >> 4) << 3;
    const int b_ri = (lane & 7) + ((lane >> 4) << 3);
    const int b_k8 = ((lane >> 3) & 1) << 3;

    for (int c = 0; c < nc; ++c) {
        if (c + 1 < nc) load_stage(c + 1, (c + 1) & 1);
        CP_COMMIT();
        CP_WAIT1();
        __syncthreads();

        const unsigned so = smb + (unsigned)(c & 1) * STAGE_B;
#pragma unroll
        for (int kk = 0; kk < 2; kk++) {
            uint32_t ah[2][4], al[2][4];
#pragma unroll
            for (int mi = 0; mi < 2; mi++) {
                unsigned ad = so +
                    (unsigned)((wm * 32 + mi * 16 + a_ri) * SST + kk * 16 + a_k8) * 2;
                ldm_x4(ah[mi], ad);
                ldm_x4(al[mi], ad + A_LOB);
            }
#pragma unroll
            for (int g = 0; g < 4; g++) {
                unsigned bd = so + B_HIB +
                    (unsigned)((wn * 64 + g * 16 + b_ri) * SST + kk * 16 + b_k8) * 2;
                uint32_t bh[4], bl[4];
                ldm_x4(bh, bd);
                ldm_x4(bl, bd + (B_LOB - B_HIB));
#pragma unroll
                for (int mi = 0; mi < 2; mi++) {
                    mma16816(acc[mi][2*g],   ah[mi], bh[0], bh[1]);
                    mma16816(acc[mi][2*g],   ah[mi], bl[0], bl[1]);
                    mma16816(acc[mi][2*g],   al[mi], bh[0], bh[1]);
                    mma16816(acc[mi][2*g+1], ah[mi], bh[2], bh[3]);
                    mma16816(acc[mi][2*g+1], ah[mi], bl[2], bl[3]);
                    mma16816(acc[mi][2*g+1], al[mi], bh[2], bh[3]);
                }
            }
        }
        __syncthreads();
    }

    // epilogue
#pragma unroll
    for (int mi = 0; mi < 2; mi++) {
        const int rb = row0 + wm * 32 + mi * 16 + (lane >> 2);
#pragma unroll
        for (int f = 0; f < 8; f++) {
            const int cc = col0 + wn * 64 + f * 8 + ((lane & 3) << 1);
            if (cc >= Nvalid) continue;
            float b0 = 0.f, b1 = 0.f;
            if (bias) { b0 = bias[cc]; b1 = bias[cc + 1]; }
            float2 v0, v1;
            v0.x = acc[mi][f][0] * scale + b0;
            v0.y = acc[mi][f][1] * scale + b1;
            v1.x = acc[mi][f][2] * scale + b0;
            v1.y = acc[mi][f][3] * scale + b1;
            *(float2*)&C[(long)rb * ldc + cc]       = v0;
            *(float2*)&C[(long)(rb + 8) * ldc + cc] = v1;
            if (Ch) {
                __nv_bfloat16 h2[2], l2[2];
                split1(v0.x, &h2[0], &l2[0]); split1(v0.y, &h2[1], &l2[1]);
                *(uint32_t*)&Ch[(long)rb * ldc + cc] = *(uint32_t*)h2;
                *(uint32_t*)&Cl[(long)rb * ldc + cc] = *(uint32_t*)l2;
                split1(v1.x, &h2[0], &l2[0]); split1(v1.y, &h2[1], &l2[1]);
                *(uint32_t*)&Ch[(long)(rb + 8) * ldc + cc] = *(uint32_t*)h2;
                *(uint32_t*)&Cl[(long)(rb + 8) * ldc + cc] = *(uint32_t*)l2;
            }
        }
    }
}

// ---------------------------------------------------------------------------
// RMSNorm rows -> bf16 hi/lo
// ---------------------------------------------------------------------------
__global__ void rmsnorm_split(const float* __restrict__ X,
                              const float* __restrict__ g,
                              __nv_bfloat16* __restrict__ H,
                              __nv_bfloat16* __restrict__ L,
                              int n, int ldin)
{
    const float* x = X + (long)blockIdx.x * ldin;
    __nv_bfloat16* h = H + (long)blockIdx.x * n;
    __nv_bfloat16* l = L + (long)blockIdx.x * n;
    __shared__ float red[256];
    float s = 0.f;
    for (int i = threadIdx.x; i < n; i += 256) { float v = x[i]; s += v * v; }
    red[threadIdx.x] = s;
    __syncthreads();
    for (int o = 128; o > 0; o >>= 1) {
        if (threadIdx.x < o) red[threadIdx.x] += red[threadIdx.x + o];
        __syncthreads();
    }
    float r = rsqrtf(red[0] / (float)n + 1e-6f);
    for (int i = threadIdx.x; i < n; i += 256)
        split1(g[i] * x[i] * r, &h[i], &l[i]);
}

// ---------------------------------------------------------------------------
// Assemble + RoPE -> bf16 hi/lo qall/kall/vt
// ---------------------------------------------------------------------------
__global__ void assemble_rope(const float* __restrict__ q,
                              const float* __restrict__ kvd,
                              const float* __restrict__ kv,
                              const int* __restrict__ pos_ids,
                              __nv_bfloat16* __restrict__ qh, __nv_bfloat16* __restrict__ ql,
                              __nv_bfloat16* __restrict__ kh, __nv_bfloat16* __restrict__ kl,
                              __nv_bfloat16* __restrict__ vh, __nv_bfloat16* __restrict__ vl)
{
    const int s = blockIdx.x;
    const int t = threadIdx.x;
    __shared__ float cs[32], sn[32], kr[64];

    if (t < 32) {
        float pos = (float)pos_ids[s];
        double freq = exp(-log(10000.0) * (double)t / 32.0);
        float arg = pos * (float)freq;
        cs[t] = cosf(arg);
        sn[t] = sinf(arg);
    }
    __syncthreads();
    if (t < 32) {
        float x0 = kvd[(long)s * KVD_W + KVLR + 2 * t];
        float x1 = kvd[(long)s * KVD_W + KVLR + 2 * t + 1];
        kr[t]      = x0 * cs[t] - x1 * sn[t];
        kr[32 + t] = x1 * cs[t] + x0 * sn[t];
    }
    __syncthreads();

    for (int idx = t; idx < HEADS * QD; idx += 256) {
        int h = idx / QD, d = idx % QD;
        float qa, ka;
        if (d < NOPE) {
            qa = q[(long)s * QUP_N + h * QD + d];
            ka = kv[(long)s * KUP_N + h * (NOPE + VD) + d];
        } else {
            int k = d - NOPE;
            int kk = k & 31;
            float x0 = q[(long)s * QUP_N + h * QD + NOPE + 2 * kk];
            float x1 = q[(long)s * QUP_N + h * QD + NOPE + 2 * kk + 1];
            qa = (k < 32) ? (x0 * cs[kk] - x1 * sn[kk])
                          : (x1 * cs[kk] + x0 * sn[kk]);
            ka = kr[k];
        }
        long o = ((long)h * S_LEN + s) * QD + d;
        split1(qa, &qh[o], &ql[o]);
        split1(ka, &kh[o], &kl[o]);
    }
    for (int idx = t; idx < HEADS * VD; idx += 256) {
        int h = idx / VD, d = idx % VD;
        long o = ((long)h * VD + d) * S_LEN + s;
        split1(kv[(long)s * KUP_N + h * (NOPE + VD) + NOPE + d], &vh[o], &vl[o]);
    }
}

// ---------------------------------------------------------------------------
// Causal softmax: fp32 in-place (full zero fill) + bf16 hi/lo out (banded)
// ---------------------------------------------------------------------------
__global__ void softmax_causal(float* __restrict__ attn,
                               __nv_bfloat16* __restrict__ H,
                               __nv_bfloat16* __restrict__ L)
{
    const long row = blockIdx.x;
    const int i = (int)(row & (S_LEN - 1));
    float* p = attn + row * S_LEN;
    __nv_bfloat16* h = H + row * S_LEN;
    __nv_bfloat16* l = L + row * S_LEN;
    const int n = i + 1;
    const int band = ((i >> 7) + 1) << 7;
    __shared__ float red[256];

    float mx = -INFINITY;
    for (int j = threadIdx.x; j < n; j += 256) mx = fmaxf(mx, p[j]);
    red[threadIdx.x] = mx;
    __syncthreads();
    for (int o = 128; o > 0; o >>= 1) {
        if (threadIdx.x < o)
            red[threadIdx.x] = fmaxf(red[threadIdx.x], red[threadIdx.x + o]);
        __syncthreads();
    }
    mx = red[0];
    __syncthreads();

    float s = 0.f;
    for (int j = threadIdx.x; j < n; j += 256) {
        float e = expf(p[j] - mx);
        p[j] = e;
        s += e;
    }
    red[threadIdx.x] = s;
    __syncthreads();
    for (int o = 128; o > 0; o >>= 1) {
        if (threadIdx.x < o) red[threadIdx.x] += red[threadIdx.x + o];
        __syncthreads();
    }
    float inv = 1.f / red[0];
    for (int j = threadIdx.x; j < n; j += 256) {
        float v = p[j] * inv;
        p[j] = v;
        split1(v, &h[j], &l[j]);
    }
    __nv_bfloat16 z = __float2bfloat16(0.f);
    for (int j = n + threadIdx.x; j < band; j += 256) { h[j] = z; l[j] = z; }
    for (int j = n + threadIdx.x; j < S_LEN; j += 256) p[j] = 0.f;
}

// ---------------------------------------------------------------------------
extern "C" void kernel_launch(void* const* d_in, const int* in_sizes, int n_in,
                              void* d_out, int out_size)
{
    (void)in_sizes; (void)n_in; (void)out_size;
    const float* hid  = (const float*)d_in[0];
    const int*   pos  = (const int*)  d_in[1];
    const float* Wqd  = (const float*)d_in[3];
    const float* bqd  = (const float*)d_in[4];
    const float* gq   = (const float*)d_in[5];
    const float* Wqu  = (const float*)d_in[6];
    const float* Wkd  = (const float*)d_in[7];
    const float* bkd  = (const float*)d_in[8];
    const float* gkv  = (const float*)d_in[9];
    const float* Wku  = (const float*)d_in[10];
    const float* Wo   = (const float*)d_in[11];

    float* out  = (float*)d_out;
    float* attn = out + (long)S_LEN * HID;

    void *pf = nullptr, *ph = nullptr, *pl = nullptr;
    cudaGetSymbolAddress(&pf, g_f32);
    cudaGetSymbolAddress(&ph, g_hi);
    cudaGetSymbolAddress(&pl, g_lo);
    float* F = (float*)pf;
    __nv_bfloat16* Hh = (__nv_bfloat16*)ph;
    __nv_bfloat16* Ll = (__nv_bfloat16*)pl;

    float* qraw = F + F_QRAW;
    float* qbuf = F + F_QBUF;
    float* kvd  = F + F_KVD;
    float* kv   = F + F_KV;
    float* ctx  = F + F_CTX;

    const int SMEM = STG * (int)STAGE_B;   // 81920
    static bool attr_done = false;
    if (!attr_done) {
        cudaFuncSetAttribute(gemm_hl<false,false>,
            cudaFuncAttributeMaxDynamicSharedMemorySize, SMEM);
        cudaFuncSetAttribute(gemm_hl<true,false>,
            cudaFuncAttributeMaxDynamicSharedMemorySize, SMEM);
        cudaFuncSetAttribute(gemm_hl<false,true>,
            cudaFuncAttributeMaxDynamicSharedMemorySize, SMEM);
        attr_done = true;
    }

    const dim3 blk(256);
    const float qk_scale = 0.07216878364870323f;   // 1/sqrt(192)

    // 0. pre-split inputs (Wkd into 640-row padded region; pad cols are
    //    computed but never stored thanks to Nvalid)
    split_hl<<<(unsigned)(((long)S_LEN*HID+1023)/1024), blk>>>(hid, Hh+O_HID, Ll+O_HID, (long)S_LEN*HID);
    split_hl<<<(unsigned)(((long)QLR*HID+1023)/1024), blk>>>(Wqd, Hh+O_WQD, Ll+O_WQD, (long)QLR*HID);
    split_hl<<<(unsigned)(((long)QUP_N*QLR+1023)/1024), blk>>>(Wqu, Hh+O_WQU, Ll+O_WQU, (long)QUP_N*QLR);
    split_hl<<<(unsigned)(((long)KVD_W*HID+1023)/1024), blk>>>(Wkd, Hh+O_WKD, Ll+O_WKD, (long)KVD_W*HID);
    split_hl<<<(unsigned)(((long)KUP_N*KVLR+1023)/1024), blk>>>(Wku, Hh+O_WKU, Ll+O_WKU, (long)KUP_N*KVLR);
    split_hl<<<(unsigned)(((long)HID*HEADS*VD+1023)/1024), blk>>>(Wo, Hh+O_WO, Ll+O_WO, (long)HID*HEADS*VD);

    // 1. qraw = hid @ Wq_down^T + bq
    gemm_hl<false,false><<<dim3(QLR/128, S_LEN/128, 1), blk, SMEM>>>(
        Hh+O_HID, Ll+O_HID, 0, Hh+O_WQD, Ll+O_WQD, 0,
        qraw, 0, nullptr, nullptr, HID, HID, HID, QLR, QLR, bqd, 1.f);
    // 2. rmsnorm -> hi/lo
    rmsnorm_split<<<S_LEN, blk>>>(qraw, gq, Hh+O_QRN, Ll+O_QRN, QLR, QLR);
    // 3. q = qrn @ Wq_up^T
    gemm_hl<false,false><<<dim3(QUP_N/128, S_LEN/128, 1), blk, SMEM>>>(
        Hh+O_QRN, Ll+O_QRN, 0, Hh+O_WQU, Ll+O_WQU, 0,
        qbuf, 0, nullptr, nullptr, QLR, QLR, QLR, QUP_N, QUP_N, nullptr, 1.f);
    // 4. kvd = hid @ Wkv_down^T + bkv  (N=576 via 640-padded weights)
    gemm_hl<false,false><<<dim3(WKD_PAD/128, S_LEN/128, 1), blk, SMEM>>>(
        Hh+O_HID, Ll+O_HID, 0, Hh+O_WKD, Ll+O_WKD, 0,
        kvd, 0, nullptr, nullptr, HID, HID, HID, KVD_W, KVD_W, bkd, 1.f);
    // 5. rmsnorm first 512 cols -> hi/lo
    rmsnorm_split<<<S_LEN, blk>>>(kvd, gkv, Hh+O_KVN, Ll+O_KVN, KVLR, KVD_W);
    // 6. kv = kvn @ Wkv_up^T
    gemm_hl<false,false><<<dim3(KUP_N/128, S_LEN/128, 1), blk, SMEM>>>(
        Hh+O_KVN, Ll+O_KVN, 0, Hh+O_WKU, Ll+O_WKU, 0,
        kv, 0, nullptr, nullptr, KVLR, KVLR, KVLR, KUP_N, KUP_N, nullptr, 1.f);
    // 7. assemble + rope -> hi/lo
    assemble_rope<<<S_LEN, blk>>>(qbuf, kvd, kv, pos,
        Hh+O_QALL, Ll+O_QALL, Hh+O_KALL, Ll+O_KALL, Hh+O_VT, Ll+O_VT);
    // 8. scores -> attn fp32 (causal block skip)
    gemm_hl<true,false><<<dim3(S_LEN/128, S_LEN/128, HEADS), blk, SMEM>>>(
        Hh+O_QALL, Ll+O_QALL, (long)S_LEN*QD,
        Hh+O_KALL, Ll+O_KALL, (long)S_LEN*QD,
        attn, (long)S_LEN*S_LEN, nullptr, nullptr,
        QD, QD, QD, S_LEN, S_LEN, nullptr, qk_scale);
    // 9. causal softmax -> fp32 + hi/lo
    softmax_causal<<<HEADS * S_LEN, blk>>>(attn, Hh+O_ATTN, Ll+O_ATTN);
    // 10. ctx = attn @ v (K clamped at diagonal); emits fp32 + hi/lo ctx
    gemm_hl<false,true><<<dim3(1, S_LEN/128, HEADS), blk, SMEM>>>(
        Hh+O_ATTN, Ll+O_ATTN, (long)S_LEN*S_LEN,
        Hh+O_VT, Ll+O_VT, (long)VD*S_LEN,
        ctx, (long)VD, Hh+O_CTX, Ll+O_CTX,
        S_LEN, S_LEN, S_LEN, HID, VD, nullptr, 1.f);
    // 11. out = ctx @ Wo^T
    gemm_hl<false,false><<<dim3(HID/128, S_LEN/128, 1), blk, SMEM>>>(
        Hh+O_CTX, Ll+O_CTX, 0, Hh+O_WO, Ll+O_WO, 0,
        out, 0, nullptr, nullptr, HID, HID, HID, HID, HID, nullptr, 1.f);
}

// round 7
// speedup vs baseline: 1.8213x; 1.8213x over previous
#include <cuda_runtime.h>
#include <cuda_fp16.h>
#include <math.h>
#include <stdint.h>

// ---------------------------------------------------------------------------
// DeepseekV2 MLA forward, B=1 S=2048 HID=2048 H=16 NOPE=128 ROPE=64 VD=128.
// Round 7: single-pass fp16 mma (was 3-pass compensated bf16). mma.sync is at
// its instruction-throughput ceiling (R5/R6 evidence), so the win is issuing
// 3x fewer mma ops. fp16 (11 mantissa bits) single-pass keeps rel_err ~2-4e-4
// (calibrated against the measured 1.58e-5 of the 2^-16 bf16 hi/lo scheme).
// GEMM: BM=128 BN=128 BK=32, 3-stage cp.async, 2 CTAs/SM, fp32 accumulate.
// ---------------------------------------------------------------------------

#define S_LEN 2048
#define HID   2048
#define HEADS 16
#define NOPE  128
#define ROPE  64
#define VD    128
#define QD    192
#define QLR   1536
#define KVLR  512
#define KVD_W (KVLR + 64)            // 576
#define QUP_N (HEADS * QD)           // 3072
#define KUP_N (HEADS * (NOPE + VD))  // 4096
#define WKD_PAD 640                  // Wkv_down rows padded to 5*128

// ---------------- fp32 scratch ----------------
#define F_QRAW 0L
#define F_QBUF (F_QRAW + (long)S_LEN * QLR)
#define F_KVD  (F_QBUF + (long)S_LEN * QUP_N)
#define F_KV   (F_KVD  + (long)S_LEN * KVD_W)
#define F_CTX  (F_KV   + (long)S_LEN * KUP_N)
#define F_TOT  (F_CTX  + (long)S_LEN * HID)

// ---------------- fp16 scratch ----------------
#define O_HID  0L
#define O_WQD  (O_HID  + (long)S_LEN * HID)
#define O_WQU  (O_WQD  + (long)QLR * HID)
#define O_WKD  (O_WQU  + (long)QUP_N * QLR)
#define O_WKU  (O_WKD  + (long)WKD_PAD * HID)   // pad rows never written;
#define O_WO   (O_WKU  + (long)KUP_N * KVLR)    // pad cols guarded by Nvalid
#define O_QRN  (O_WO   + (long)HID * (HEADS * VD))
#define O_KVN  (O_QRN  + (long)S_LEN * QLR)
#define O_QALL (O_KVN  + (long)S_LEN * KVLR)
#define O_KALL (O_QALL + (long)HEADS * S_LEN * QD)
#define O_VT   (O_KALL + (long)HEADS * S_LEN * QD)
#define O_ATTN (O_VT   + (long)HEADS * VD * S_LEN)
#define O_CTX  (O_ATTN + (long)HEADS * S_LEN * S_LEN)
#define O_TOT  (O_CTX  + (long)S_LEN * HID)

__device__ __align__(256) float  g_f32[F_TOT];
__device__ __align__(256) __half g_h16[O_TOT];

// ---------------------------------------------------------------------------
__device__ __forceinline__ unsigned smem_u32(const void* p) {
    return (unsigned)__cvta_generic_to_shared(p);
}
__device__ __forceinline__ void ldm_x4(uint32_t r[4], unsigned addr) {
    asm volatile("ldmatrix.sync.aligned.m8n8.x4.shared.b16 {%0,%1,%2,%3}, [%4];"
                 : "=r"(r[0]), "=r"(r[1]), "=r"(r[2]), "=r"(r[3]) : "r"(addr));
}
__device__ __forceinline__ void mma16816(float d[4], const uint32_t a[4],
                                         const uint32_t b0, const uint32_t b1) {
    asm volatile(
        "mma.sync.aligned.m16n8k16.row.col.f32.f16.f16.f32 "
        "{%0,%1,%2,%3}, {%4,%5,%6,%7}, {%8,%9}, {%0,%1,%2,%3};"
        : "+f"(d[0]), "+f"(d[1]), "+f"(d[2]), "+f"(d[3])
        : "r"(a[0]), "r"(a[1]), "r"(a[2]), "r"(a[3]), "r"(b0), "r"(b1));
}
__device__ __forceinline__ void cp16(unsigned dst, const void* src) {
    asm volatile("cp.async.cg.shared.global [%0], [%1], 16;"
                 :: "r"(dst), "l"(src));
}
#define CP_COMMIT() asm volatile("cp.async.commit_group;" ::: "memory")
#define CP_WAIT2()  asm volatile("cp.async.wait_group 2;" ::: "memory")

// ---------------------------------------------------------------------------
// elementwise fp32 -> fp16
// ---------------------------------------------------------------------------
__global__ void cvt_h(const float* __restrict__ x, __half* __restrict__ h,
                      long n)
{
    long i = ((long)blockIdx.x * 256 + threadIdx.x) * 4;
    if (i >= n) return;
    float4 v = *(const float4*)(x + i);
    __half2 a = __floats2half2_rn(v.x, v.y);
    __half2 b = __floats2half2_rn(v.z, v.w);
    uint2 u;
    u.x = *(uint32_t*)&a; u.y = *(uint32_t*)&b;
    *(uint2*)(h + i) = u;
}

// ---------------------------------------------------------------------------
// Tensor-core GEMM (mma.sync fp16): C[M,N] = scale*(A[M,K] @ B[N,K]^T)+bias.
// BM=128, BN=128, BK=32, 256 threads (8 warps: 4m x 2n, warp tile 32x64).
// 3-stage cp.async pipeline, 2 CTAs/SM. Optional fp16 C copy.
// ---------------------------------------------------------------------------
#define SST 40                        // smem row stride, halves (80 B)
#define STG 3
#define STAGE_B 20480u                // 256 rows * 80 B
#define B_OFF   10240u                // B tile at row 128

template<bool CSKIP, bool CKLIM>
__global__ __launch_bounds__(256, 2)
void gemm_h(const __half* __restrict__ Ag, long sA,
            const __half* __restrict__ Bg, long sB,
            float* __restrict__ C, long sC,
            __half* __restrict__ Ch,
            int K, int lda, int ldb, int ldc, int Nvalid,
            const float* __restrict__ bias, float scale)
{
    extern __shared__ __half sm[];

    const int bz = blockIdx.z;
    Ag += (long)bz * sA;
    Bg += (long)bz * sB;
    C  += (long)bz * sC;
    if (Ch) Ch += (long)bz * sC;

    const int row0 = blockIdx.y * 128;
    const int col0 = blockIdx.x * 128;
    if (CSKIP && col0 >= row0 + 128) return;

    const int kEnd = CKLIM ? min(K, row0 + 128) : K;
    const int nc = kEnd >> 5;

    const int tid = threadIdx.x;
    const int wid = tid >> 5, lane = tid & 31;
    const int wm = wid & 3, wn = wid >> 2;

    // global load geometry: row tid/2, 32B chunk at (tid&1)*32B
    const int gr  = tid >> 1;
    const int gcb = (tid & 1) * 16;                  // halves (32 B)
    const __half* pA = Ag + (long)(row0 + gr) * lda + gcb;
    const __half* pB = Bg + (long)(col0 + gr) * ldb + gcb;

    const unsigned smb  = smem_u32(sm);
    const unsigned soff = (unsigned)(gr * SST + gcb) * 2;

    float acc[2][8][4];
#pragma unroll
    for (int i = 0; i < 2; i++)
#pragma unroll
        for (int j = 0; j < 8; j++)
#pragma unroll
            for (int k = 0; k < 4; k++) acc[i][j][k] = 0.f;

    auto load_stage = [&](int kc, int slot) {
        const int k0 = kc << 5;
        const unsigned so = smb + (unsigned)slot * STAGE_B + soff;
        cp16(so,              pA + k0);
        cp16(so + 16,         pA + k0 + 8);
        cp16(so + B_OFF,      pB + k0);
        cp16(so + B_OFF + 16, pB + k0 + 8);
    };

    // prologue: stages 0,1 -> slots 0,1
#pragma unroll
    for (int s = 0; s < STG - 1; s++) {
        if (s < nc) load_stage(s, s);
        CP_COMMIT();
    }

    // ldmatrix per-thread offsets
    const int a_ri = lane & 15;
    const int a_k8 = (lane >> 4) << 3;
    const int b_ri = (lane & 7) + ((lane >> 4) << 3);
    const int b_k8 = ((lane >> 3) & 1) << 3;

    for (int c = 0; c < nc; ++c) {
        const int nx = c + STG - 1;
        if (nx < nc) load_stage(nx, nx % STG);   // slot freed by iter c-1
        CP_COMMIT();
        CP_WAIT2();                              // stage c complete
        __syncthreads();

        const unsigned so = smb + (unsigned)(c % STG) * STAGE_B;
#pragma unroll
        for (int kk = 0; kk < 2; kk++) {
            uint32_t af[2][4];
#pragma unroll
            for (int mi = 0; mi < 2; mi++) {
                unsigned ad = so +
                    (unsigned)((wm * 32 + mi * 16 + a_ri) * SST + kk * 16 + a_k8) * 2;
                ldm_x4(af[mi], ad);
            }
#pragma unroll
            for (int g = 0; g < 4; g++) {
                unsigned bd = so + B_OFF +
                    (unsigned)((wn * 64 + g * 16 + b_ri) * SST + kk * 16 + b_k8) * 2;
                uint32_t bf[4];
                ldm_x4(bf, bd);
#pragma unroll
                for (int mi = 0; mi < 2; mi++) {
                    mma16816(acc[mi][2*g],   af[mi], bf[0], bf[1]);
                    mma16816(acc[mi][2*g+1], af[mi], bf[2], bf[3]);
                }
            }
        }
        __syncthreads();
    }

    // epilogue
#pragma unroll
    for (int mi = 0; mi < 2; mi++) {
        const int rb = row0 + wm * 32 + mi * 16 + (lane >> 2);
#pragma unroll
        for (int f = 0; f < 8; f++) {
            const int cc = col0 + wn * 64 + f * 8 + ((lane & 3) << 1);
            if (cc >= Nvalid) continue;
            float b0 = 0.f, b1 = 0.f;
            if (bias) { b0 = bias[cc]; b1 = bias[cc + 1]; }
            float2 v0, v1;
            v0.x = acc[mi][f][0] * scale + b0;
            v0.y = acc[mi][f][1] * scale + b1;
            v1.x = acc[mi][f][2] * scale + b0;
            v1.y = acc[mi][f][3] * scale + b1;
            *(float2*)&C[(long)rb * ldc + cc]       = v0;
            *(float2*)&C[(long)(rb + 8) * ldc + cc] = v1;
            if (Ch) {
                __half2 h0 = __floats2half2_rn(v0.x, v0.y);
                __half2 h1 = __floats2half2_rn(v1.x, v1.y);
                *(uint32_t*)&Ch[(long)rb * ldc + cc]       = *(uint32_t*)&h0;
                *(uint32_t*)&Ch[(long)(rb + 8) * ldc + cc] = *(uint32_t*)&h1;
            }
        }
    }
}

// ---------------------------------------------------------------------------
// RMSNorm rows -> fp16
// ---------------------------------------------------------------------------
__global__ void rmsnorm_h(const float* __restrict__ X,
                          const float* __restrict__ g,
                          __half* __restrict__ H, int n, int ldin)
{
    const float* x = X + (long)blockIdx.x * ldin;
    __half* h = H + (long)blockIdx.x * n;
    __shared__ float red[256];
    float s = 0.f;
    for (int i = threadIdx.x; i < n; i += 256) { float v = x[i]; s += v * v; }
    red[threadIdx.x] = s;
    __syncthreads();
    for (int o = 128; o > 0; o >>= 1) {
        if (threadIdx.x < o) red[threadIdx.x] += red[threadIdx.x + o];
        __syncthreads();
    }
    float r = rsqrtf(red[0] / (float)n + 1e-6f);
    for (int i = threadIdx.x; i < n; i += 256)
        h[i] = __float2half_rn(g[i] * x[i] * r);
}

// ---------------------------------------------------------------------------
// Assemble + RoPE -> fp16 qall/kall/vt
// ---------------------------------------------------------------------------
__global__ void assemble_rope(const float* __restrict__ q,
                              const float* __restrict__ kvd,
                              const float* __restrict__ kv,
                              const int* __restrict__ pos_ids,
                              __half* __restrict__ qa,
                              __half* __restrict__ ka,
                              __half* __restrict__ va)
{
    const int s = blockIdx.x;
    const int t = threadIdx.x;
    __shared__ float cs[32], sn[32], kr[64];

    if (t < 32) {
        float pos = (float)pos_ids[s];
        double freq = exp(-log(10000.0) * (double)t / 32.0);
        float arg = pos * (float)freq;
        cs[t] = cosf(arg);
        sn[t] = sinf(arg);
    }
    __syncthreads();
    if (t < 32) {
        float x0 = kvd[(long)s * KVD_W + KVLR + 2 * t];
        float x1 = kvd[(long)s * KVD_W + KVLR + 2 * t + 1];
        kr[t]      = x0 * cs[t] - x1 * sn[t];
        kr[32 + t] = x1 * cs[t] + x0 * sn[t];
    }
    __syncthreads();

    for (int idx = t; idx < HEADS * QD; idx += 256) {
        int h = idx / QD, d = idx % QD;
        float qv, kvv;
        if (d < NOPE) {
            qv  = q[(long)s * QUP_N + h * QD + d];
            kvv = kv[(long)s * KUP_N + h * (NOPE + VD) + d];
        } else {
            int k = d - NOPE;
            int kk = k & 31;
            float x0 = q[(long)s * QUP_N + h * QD + NOPE + 2 * kk];
            float x1 = q[(long)s * QUP_N + h * QD + NOPE + 2 * kk + 1];
            qv = (k < 32) ? (x0 * cs[kk] - x1 * sn[kk])
                          : (x1 * cs[kk] + x0 * sn[kk]);
            kvv = kr[k];
        }
        long o = ((long)h * S_LEN + s) * QD + d;
        qa[o] = __float2half_rn(qv);
        ka[o] = __float2half_rn(kvv);
    }
    for (int idx = t; idx < HEADS * VD; idx += 256) {
        int h = idx / VD, d = idx % VD;
        va[((long)h * VD + d) * S_LEN + s] =
            __float2half_rn(kv[(long)s * KUP_N + h * (NOPE + VD) + NOPE + d]);
    }
}

// ---------------------------------------------------------------------------
// Causal softmax: fp32 in-place (full zero fill) + fp16 out (banded)
// ---------------------------------------------------------------------------
__global__ void softmax_causal(float* __restrict__ attn,
                               __half* __restrict__ H)
{
    const long row = blockIdx.x;
    const int i = (int)(row & (S_LEN - 1));
    float* p = attn + row * S_LEN;
    __half* h = H + row * S_LEN;
    const int n = i + 1;
    const int band = ((i >> 7) + 1) << 7;
    __shared__ float red[256];

    float mx = -INFINITY;
    for (int j = threadIdx.x; j < n; j += 256) mx = fmaxf(mx, p[j]);
    red[threadIdx.x] = mx;
    __syncthreads();
    for (int o = 128; o > 0; o >>= 1) {
        if (threadIdx.x < o)
            red[threadIdx.x] = fmaxf(red[threadIdx.x], red[threadIdx.x + o]);
        __syncthreads();
    }
    mx = red[0];
    __syncthreads();

    float s = 0.f;
    for (int j = threadIdx.x; j < n; j += 256) {
        float e = expf(p[j] - mx);
        p[j] = e;
        s += e;
    }
    red[threadIdx.x] = s;
    __syncthreads();
    for (int o = 128; o > 0; o >>= 1) {
        if (threadIdx.x < o) red[threadIdx.x] += red[threadIdx.x + o];
        __syncthreads();
    }
    float inv = 1.f / red[0];
    for (int j = threadIdx.x; j < n; j += 256) {
        float v = p[j] * inv;
        p[j] = v;
        h[j] = __float2half_rn(v);
    }
    __half z = __float2half_rn(0.f);
    for (int j = n + threadIdx.x; j < band; j += 256) h[j] = z;
    for (int j = n + threadIdx.x; j < S_LEN; j += 256) p[j] = 0.f;
}

// ---------------------------------------------------------------------------
extern "C" void kernel_launch(void* const* d_in, const int* in_sizes, int n_in,
                              void* d_out, int out_size)
{
    (void)in_sizes; (void)n_in; (void)out_size;
    const float* hid  = (const float*)d_in[0];
    const int*   pos  = (const int*)  d_in[1];
    const float* Wqd  = (const float*)d_in[3];
    const float* bqd  = (const float*)d_in[4];
    const float* gq   = (const float*)d_in[5];
    const float* Wqu  = (const float*)d_in[6];
    const float* Wkd  = (const float*)d_in[7];
    const float* bkd  = (const float*)d_in[8];
    const float* gkv  = (const float*)d_in[9];
    const float* Wku  = (const float*)d_in[10];
    const float* Wo   = (const float*)d_in[11];

    float* out  = (float*)d_out;
    float* attn = out + (long)S_LEN * HID;

    void *pf = nullptr, *ph = nullptr;
    cudaGetSymbolAddress(&pf, g_f32);
    cudaGetSymbolAddress(&ph, g_h16);
    float*  F = (float*)pf;
    __half* H = (__half*)ph;

    float* qraw = F + F_QRAW;
    float* qbuf = F + F_QBUF;
    float* kvd  = F + F_KVD;
    float* kv   = F + F_KV;
    float* ctx  = F + F_CTX;

    const int SMEM = STG * (int)STAGE_B;   // 61440
    static bool attr_done = false;
    if (!attr_done) {
        cudaFuncSetAttribute(gemm_h<false,false>,
            cudaFuncAttributeMaxDynamicSharedMemorySize, SMEM);
        cudaFuncSetAttribute(gemm_h<true,false>,
            cudaFuncAttributeMaxDynamicSharedMemorySize, SMEM);
        cudaFuncSetAttribute(gemm_h<false,true>,
            cudaFuncAttributeMaxDynamicSharedMemorySize, SMEM);
        attr_done = true;
    }

    const dim3 blk(256);
    const float qk_scale = 0.07216878364870323f;   // 1/sqrt(192)

    // 0. convert inputs to fp16 (Wkd into 640-row padded region)
    cvt_h<<<(unsigned)(((long)S_LEN*HID+1023)/1024), blk>>>(hid, H+O_HID, (long)S_LEN*HID);
    cvt_h<<<(unsigned)(((long)QLR*HID+1023)/1024), blk>>>(Wqd, H+O_WQD, (long)QLR*HID);
    cvt_h<<<(unsigned)(((long)QUP_N*QLR+1023)/1024), blk>>>(Wqu, H+O_WQU, (long)QUP_N*QLR);
    cvt_h<<<(unsigned)(((long)KVD_W*HID+1023)/1024), blk>>>(Wkd, H+O_WKD, (long)KVD_W*HID);
    cvt_h<<<(unsigned)(((long)KUP_N*KVLR+1023)/1024), blk>>>(Wku, H+O_WKU, (long)KUP_N*KVLR);
    cvt_h<<<(unsigned)(((long)HID*HEADS*VD+1023)/1024), blk>>>(Wo, H+O_WO, (long)HID*HEADS*VD);

    // 1. qraw = hid @ Wq_down^T + bq
    gemm_h<false,false><<<dim3(QLR/128, S_LEN/128, 1), blk, SMEM>>>(
        H+O_HID, 0, H+O_WQD, 0, qraw, 0, nullptr,
        HID, HID, HID, QLR, QLR, bqd, 1.f);
    // 2. rmsnorm -> fp16
    rmsnorm_h<<<S_LEN, blk>>>(qraw, gq, H+O_QRN, QLR, QLR);
    // 3. q = qrn @ Wq_up^T
    gemm_h<false,false><<<dim3(QUP_N/128, S_LEN/128, 1), blk, SMEM>>>(
        H+O_QRN, 0, H+O_WQU, 0, qbuf, 0, nullptr,
        QLR, QLR, QLR, QUP_N, QUP_N, nullptr, 1.f);
    // 4. kvd = hid @ Wkv_down^T + bkv  (N=576 via 640-padded weights)
    gemm_h<false,false><<<dim3(WKD_PAD/128, S_LEN/128, 1), blk, SMEM>>>(
        H+O_HID, 0, H+O_WKD, 0, kvd, 0, nullptr,
        HID, HID, HID, KVD_W, KVD_W, bkd, 1.f);
    // 5. rmsnorm first 512 cols -> fp16
    rmsnorm_h<<<S_LEN, blk>>>(kvd, gkv, H+O_KVN, KVLR, KVD_W);
    // 6. kv = kvn @ Wkv_up^T
    gemm_h<false,false><<<dim3(KUP_N/128, S_LEN/128, 1), blk, SMEM>>>(
        H+O_KVN, 0, H+O_WKU, 0, kv, 0, nullptr,
        KVLR, KVLR, KVLR, KUP_N, KUP_N, nullptr, 1.f);
    // 7. assemble + rope -> fp16
    assemble_rope<<<S_LEN, blk>>>(qbuf, kvd, kv, pos,
                                  H+O_QALL, H+O_KALL, H+O_VT);
    // 8. scores -> attn fp32 (causal block skip)
    gemm_h<true,false><<<dim3(S_LEN/128, S_LEN/128, HEADS), blk, SMEM>>>(
        H+O_QALL, (long)S_LEN*QD, H+O_KALL, (long)S_LEN*QD,
        attn, (long)S_LEN*S_LEN, nullptr,
        QD, QD, QD, S_LEN, S_LEN, nullptr, qk_scale);
    // 9. causal softmax -> fp32 + fp16
    softmax_causal<<<HEADS * S_LEN, blk>>>(attn, H+O_ATTN);
    // 10. ctx = attn @ v (K clamped at diagonal); emits fp32 + fp16 ctx
    gemm_h<false,true><<<dim3(1, S_LEN/128, HEADS), blk, SMEM>>>(
        H+O_ATTN, (long)S_LEN*S_LEN, H+O_VT, (long)VD*S_LEN,
        ctx, (long)VD, H+O_CTX,
        S_LEN, S_LEN, S_LEN, HID, VD, nullptr, 1.f);
    // 11. out = ctx @ Wo^T
    gemm_h<false,false><<<dim3(HID/128, S_LEN/128, 1), blk, SMEM>>>(
        H+O_CTX, 0, H+O_WO, 0, out, 0, nullptr,
        HID, HID, HID, HID, HID, nullptr, 1.f);
}

// round 8
// speedup vs baseline: 2.0948x; 1.1502x over previous
#include <cuda_runtime.h>
#include <cuda_fp16.h>
#include <math.h>
#include <stdint.h>

// ---------------------------------------------------------------------------
// DeepseekV2 MLA forward, B=1 S=2048 HID=2048 H=16 NOPE=128 ROPE=64 VD=128.
// Round 8: T0 (non-mma) reduction. Single-read smem softmax; PV becomes an
// NN gemm via ldmatrix.trans reading an fp16 kv copy (kills the uncoalesced
// vt transpose); GEMM mainloop down to one __syncthreads per K-chunk.
// GEMM: fp16 single-pass mma.sync, BM=128 BN=128 BK=32, 3-stage cp.async.
// ---------------------------------------------------------------------------

#define S_LEN 2048
#define HID   2048
#define HEADS 16
#define NOPE  128
#define ROPE  64
#define VD    128
#define QD    192
#define QLR   1536
#define KVLR  512
#define KVD_W (KVLR + 64)            // 576
#define QUP_N (HEADS * QD)           // 3072
#define KUP_N (HEADS * (NOPE + VD))  // 4096
#define WKD_PAD 640                  // Wkv_down rows padded to 5*128

// ---------------- fp32 scratch ----------------
#define F_QRAW 0L
#define F_QBUF (F_QRAW + (long)S_LEN * QLR)
#define F_KVD  (F_QBUF + (long)S_LEN * QUP_N)
#define F_KV   (F_KVD  + (long)S_LEN * KVD_W)
#define F_CTX  (F_KV   + (long)S_LEN * KUP_N)
#define F_TOT  (F_CTX  + (long)S_LEN * HID)

// ---------------- fp16 scratch ----------------
#define O_HID  0L
#define O_WQD  (O_HID  + (long)S_LEN * HID)
#define O_WQU  (O_WQD  + (long)QLR * HID)
#define O_WKD  (O_WQU  + (long)QUP_N * QLR)
#define O_WKU  (O_WKD  + (long)WKD_PAD * HID)
#define O_WO   (O_WKU  + (long)KUP_N * KVLR)
#define O_QRN  (O_WO   + (long)HID * (HEADS * VD))
#define O_KVN  (O_QRN  + (long)S_LEN * QLR)
#define O_QALL (O_KVN  + (long)S_LEN * KVLR)
#define O_KALL (O_QALL + (long)HEADS * S_LEN * QD)
#define O_KV16 (O_KALL + (long)HEADS * S_LEN * QD)     // fp16 copy of kv
#define O_ATTN (O_KV16 + (long)S_LEN * KUP_N)
#define O_CTX  (O_ATTN + (long)HEADS * S_LEN * S_LEN)
#define O_TOT  (O_CTX  + (long)S_LEN * HID)

__device__ __align__(256) float  g_f32[F_TOT];
__device__ __align__(256) __half g_h16[O_TOT];

// ---------------------------------------------------------------------------
__device__ __forceinline__ unsigned smem_u32(const void* p) {
    return (unsigned)__cvta_generic_to_shared(p);
}
__device__ __forceinline__ void ldm_x4(uint32_t r[4], unsigned addr) {
    asm volatile("ldmatrix.sync.aligned.m8n8.x4.shared.b16 {%0,%1,%2,%3}, [%4];"
                 : "=r"(r[0]), "=r"(r[1]), "=r"(r[2]), "=r"(r[3]) : "r"(addr));
}
__device__ __forceinline__ void ldm_x4t(uint32_t r[4], unsigned addr) {
    asm volatile("ldmatrix.sync.aligned.m8n8.x4.trans.shared.b16 {%0,%1,%2,%3}, [%4];"
                 : "=r"(r[0]), "=r"(r[1]), "=r"(r[2]), "=r"(r[3]) : "r"(addr));
}
__device__ __forceinline__ void mma16816(float d[4], const uint32_t a[4],
                                         const uint32_t b0, const uint32_t b1) {
    asm volatile(
        "mma.sync.aligned.m16n8k16.row.col.f32.f16.f16.f32 "
        "{%0,%1,%2,%3}, {%4,%5,%6,%7}, {%8,%9}, {%0,%1,%2,%3};"
        : "+f"(d[0]), "+f"(d[1]), "+f"(d[2]), "+f"(d[3])
        : "r"(a[0]), "r"(a[1]), "r"(a[2]), "r"(a[3]), "r"(b0), "r"(b1));
}
__device__ __forceinline__ void cp16(unsigned dst, const void* src) {
    asm volatile("cp.async.cg.shared.global [%0], [%1], 16;"
                 :: "r"(dst), "l"(src));
}
#define CP_COMMIT() asm volatile("cp.async.commit_group;" ::: "memory")
#define CP_WAIT1()  asm volatile("cp.async.wait_group 1;" ::: "memory")

// ---------------------------------------------------------------------------
// elementwise fp32 -> fp16
// ---------------------------------------------------------------------------
__global__ void cvt_h(const float* __restrict__ x, __half* __restrict__ h,
                      long n)
{
    long i = ((long)blockIdx.x * 256 + threadIdx.x) * 4;
    if (i >= n) return;
    float4 v = *(const float4*)(x + i);
    __half2 a = __floats2half2_rn(v.x, v.y);
    __half2 b = __floats2half2_rn(v.z, v.w);
    uint2 u;
    u.x = *(uint32_t*)&a; u.y = *(uint32_t*)&b;
    *(uint2*)(h + i) = u;
}

// ---------------------------------------------------------------------------
// Tensor-core GEMM (mma.sync fp16):
//   BTRANS=0: C[M,N] = scale*(A[M,K] @ B[N,K]^T)+bias  (B row-major [N][K])
//   BTRANS=1: C[M,N] = scale*(A[M,K] @ B[K,N])+bias    (B row-major [K][N],
//             fragments via ldmatrix.trans)
// BM=128, BN=128, BK=32, 256 threads (8 warps: 4m x 2n, warp tile 32x64).
// 3-stage cp.async pipeline, one __syncthreads per chunk, 2 CTAs/SM.
// ---------------------------------------------------------------------------
#define SST 40                        // A smem row stride, halves (80 B)
#define BSTR 136                      // BTRANS B smem row stride, halves
#define STG 3
#define B_OFF 10240u                  // B tile offset within stage

template<bool CSKIP, bool CKLIM, bool BTRANS>
__global__ __launch_bounds__(256, 2)
void gemm_h(const __half* __restrict__ Ag, long sA,
            const __half* __restrict__ Bg, long sB,
            float* __restrict__ C, long sC,
            __half* __restrict__ Ch,
            int K, int lda, int ldb, int ldc, int Nvalid,
            const float* __restrict__ bias, float scale)
{
    constexpr unsigned STAGE = BTRANS ? (B_OFF + 32u * BSTR * 2u)   // 18944
                                      : (B_OFF + 128u * SST * 2u);  // 20480
    extern __shared__ __half sm[];

    const int bz = blockIdx.z;
    Ag += (long)bz * sA;
    Bg += (long)bz * sB;
    C  += (long)bz * sC;
    if (Ch) Ch += (long)bz * sC;

    const int row0 = blockIdx.y * 128;
    const int col0 = blockIdx.x * 128;
    if (CSKIP && col0 >= row0 + 128) return;

    const int kEnd = CKLIM ? min(K, row0 + 128) : K;
    const int nc = kEnd >> 5;

    const int tid = threadIdx.x;
    const int wid = tid >> 5, lane = tid & 31;
    const int wm = wid & 3, wn = wid >> 2;

    // A global load: row tid/2, 32B chunk at (tid&1)*32B
    const int gr  = tid >> 1;
    const int gcb = (tid & 1) * 16;
    const __half* pA = Ag + (long)(row0 + gr) * lda + gcb;
    const unsigned smb   = smem_u32(sm);
    const unsigned aoff  = (unsigned)(gr * SST + gcb) * 2;

    // B global load
    const __half* pB;
    unsigned boff;
    if (BTRANS) {
        const int br = tid >> 3;            // 0..31 (k rows)
        const int bc = (tid & 7) * 16;      // halves within 128-col row
        pB = Bg + (long)br * ldb + col0 + bc;
        boff = B_OFF + (unsigned)(br * BSTR + bc) * 2;
    } else {
        pB = Bg + (long)(col0 + gr) * ldb + gcb;
        boff = B_OFF + (unsigned)(gr * SST + gcb) * 2;
    }

    float acc[2][8][4];
#pragma unroll
    for (int i = 0; i < 2; i++)
#pragma unroll
        for (int j = 0; j < 8; j++)
#pragma unroll
            for (int k = 0; k < 4; k++) acc[i][j][k] = 0.f;

    auto load_stage = [&](int kc, int slot) {
        const int k0 = kc << 5;
        const unsigned so = smb + (unsigned)slot * STAGE;
        cp16(so + aoff,      pA + k0);
        cp16(so + aoff + 16, pA + k0 + 8);
        if (BTRANS) {
            const __half* b = pB + (long)k0 * ldb;
            cp16(so + boff,      b);
            cp16(so + boff + 16, b + 8);
        } else {
            cp16(so + boff,      pB + k0);
            cp16(so + boff + 16, pB + k0 + 8);
        }
    };

    // prologue: stages 0..STG-2
#pragma unroll
    for (int s = 0; s < STG - 1; s++) {
        if (s < nc) load_stage(s, s);
        CP_COMMIT();
    }

    // per-thread ldmatrix offsets
    const int a_ri = lane & 15;
    const int a_k8 = (lane >> 4) << 3;
    const int b_ri = (lane & 7) + ((lane >> 4) << 3);   // non-trans
    const int b_k8 = ((lane >> 3) & 1) << 3;
    const int t_kr = lane & 15;                          // trans: k row
    const int t_n8 = ((lane >> 4) & 1) << 3;             // trans: n offset

    for (int c = 0; c < nc; ++c) {
        CP_WAIT1();          // stage c's group complete (all but newest 1)
        __syncthreads();

        const unsigned so = smb + (unsigned)(c % STG) * STAGE;
#pragma unroll
        for (int kk = 0; kk < 2; kk++) {
            uint32_t af[2][4];
#pragma unroll
            for (int mi = 0; mi < 2; mi++) {
                unsigned ad = so +
                    (unsigned)((wm * 32 + mi * 16 + a_ri) * SST + kk * 16 + a_k8) * 2;
                ldm_x4(af[mi], ad);
            }
#pragma unroll
            for (int g = 0; g < 4; g++) {
                uint32_t bf[4];
                if (BTRANS) {
                    unsigned bd = so + B_OFF +
                        (unsigned)((kk * 16 + t_kr) * BSTR +
                                   wn * 64 + g * 16 + t_n8) * 2;
                    ldm_x4t(bf, bd);
                } else {
                    unsigned bd = so + B_OFF +
                        (unsigned)((wn * 64 + g * 16 + b_ri) * SST + kk * 16 + b_k8) * 2;
                    ldm_x4(bf, bd);
                }
#pragma unroll
                for (int mi = 0; mi < 2; mi++) {
                    mma16816(acc[mi][2*g],   af[mi], bf[0], bf[1]);
                    mma16816(acc[mi][2*g+1], af[mi], bf[2], bf[3]);
                }
            }
        }
        // prefetch stage c+STG-1 into the slot freed by iteration c-1
        const int nx = c + STG - 1;
        if (nx < nc) load_stage(nx, nx % STG);
        CP_COMMIT();
    }

    // epilogue
#pragma unroll
    for (int mi = 0; mi < 2; mi++) {
        const int rb = row0 + wm * 32 + mi * 16 + (lane >> 2);
#pragma unroll
        for (int f = 0; f < 8; f++) {
            const int cc = col0 + wn * 64 + f * 8 + ((lane & 3) << 1);
            if (cc >= Nvalid) continue;
            float b0 = 0.f, b1 = 0.f;
            if (bias) { b0 = bias[cc]; b1 = bias[cc + 1]; }
            float2 v0, v1;
            v0.x = acc[mi][f][0] * scale + b0;
            v0.y = acc[mi][f][1] * scale + b1;
            v1.x = acc[mi][f][2] * scale + b0;
            v1.y = acc[mi][f][3] * scale + b1;
            *(float2*)&C[(long)rb * ldc + cc]       = v0;
            *(float2*)&C[(long)(rb + 8) * ldc + cc] = v1;
            if (Ch) {
                __half2 h0 = __floats2half2_rn(v0.x, v0.y);
                __half2 h1 = __floats2half2_rn(v1.x, v1.y);
                *(uint32_t*)&Ch[(long)rb * ldc + cc]       = *(uint32_t*)&h0;
                *(uint32_t*)&Ch[(long)(rb + 8) * ldc + cc] = *(uint32_t*)&h1;
            }
        }
    }
}

// ---------------------------------------------------------------------------
// RMSNorm rows -> fp16
// ---------------------------------------------------------------------------
__global__ void rmsnorm_h(const float* __restrict__ X,
                          const float* __restrict__ g,
                          __half* __restrict__ H, int n, int ldin)
{
    const float* x = X + (long)blockIdx.x * ldin;
    __half* h = H + (long)blockIdx.x * n;
    __shared__ float red[256];
    float s = 0.f;
    for (int i = threadIdx.x; i < n; i += 256) { float v = x[i]; s += v * v; }
    red[threadIdx.x] = s;
    __syncthreads();
    for (int o = 128; o > 0; o >>= 1) {
        if (threadIdx.x < o) red[threadIdx.x] += red[threadIdx.x + o];
        __syncthreads();
    }
    float r = rsqrtf(red[0] / (float)n + 1e-6f);
    for (int i = threadIdx.x; i < n; i += 256)
        h[i] = __float2half_rn(g[i] * x[i] * r);
}

// ---------------------------------------------------------------------------
// Assemble + RoPE -> fp16 qall/kall (vt eliminated; PV reads kv16 directly)
// ---------------------------------------------------------------------------
__global__ void assemble_rope(const float* __restrict__ q,
                              const float* __restrict__ kvd,
                              const float* __restrict__ kv,
                              const int* __restrict__ pos_ids,
                              __half* __restrict__ qa,
                              __half* __restrict__ ka)
{
    const int s = blockIdx.x;
    const int t = threadIdx.x;
    __shared__ float cs[32], sn[32], kr[64];

    if (t < 32) {
        float pos = (float)pos_ids[s];
        double freq = exp(-log(10000.0) * (double)t / 32.0);
        float arg = pos * (float)freq;
        cs[t] = cosf(arg);
        sn[t] = sinf(arg);
    }
    __syncthreads();
    if (t < 32) {
        float x0 = kvd[(long)s * KVD_W + KVLR + 2 * t];
        float x1 = kvd[(long)s * KVD_W + KVLR + 2 * t + 1];
        kr[t]      = x0 * cs[t] - x1 * sn[t];
        kr[32 + t] = x1 * cs[t] + x0 * sn[t];
    }
    __syncthreads();

    for (int idx = t; idx < HEADS * QD; idx += 256) {
        int h = idx / QD, d = idx % QD;
        float qv, kvv;
        if (d < NOPE) {
            qv  = q[(long)s * QUP_N + h * QD + d];
            kvv = kv[(long)s * KUP_N + h * (NOPE + VD) + d];
        } else {
            int k = d - NOPE;
            int kk = k & 31;
            float x0 = q[(long)s * QUP_N + h * QD + NOPE + 2 * kk];
            float x1 = q[(long)s * QUP_N + h * QD + NOPE + 2 * kk + 1];
            qv = (k < 32) ? (x0 * cs[kk] - x1 * sn[kk])
                          : (x1 * cs[kk] + x0 * sn[kk]);
            kvv = kr[k];
        }
        long o = ((long)h * S_LEN + s) * QD + d;
        qa[o] = __float2half_rn(qv);
        ka[o] = __float2half_rn(kvv);
    }
}

// ---------------------------------------------------------------------------
// Causal softmax: single DRAM read. Row staged in smem (<=8KB), then
// max/exp/sum/normalize; writes fp32 (full row incl. zeros) + fp16 (banded).
// ---------------------------------------------------------------------------
__global__ void softmax_causal(float* __restrict__ attn,
                               __half* __restrict__ H)
{
    const long row = blockIdx.x;
    const int i = (int)(row & (S_LEN - 1));
    float* p = attn + row * S_LEN;
    __half* h = H + row * S_LEN;
    const int n = i + 1;
    const int band = ((i >> 7) + 1) << 7;
    __shared__ float srow[S_LEN];
    __shared__ float red[256];

    for (int j = threadIdx.x; j < n; j += 256) srow[j] = p[j];
    __syncthreads();

    float mx = -INFINITY;
    for (int j = threadIdx.x; j < n; j += 256) mx = fmaxf(mx, srow[j]);
    red[threadIdx.x] = mx;
    __syncthreads();
    for (int o = 128; o > 0; o >>= 1) {
        if (threadIdx.x < o)
            red[threadIdx.x] = fmaxf(red[threadIdx.x], red[threadIdx.x + o]);
        __syncthreads();
    }
    mx = red[0];
    __syncthreads();

    float s = 0.f;
    for (int j = threadIdx.x; j < n; j += 256) {
        float e = expf(srow[j] - mx);
        srow[j] = e;
        s += e;
    }
    red[threadIdx.x] = s;
    __syncthreads();
    for (int o = 128; o > 0; o >>= 1) {
        if (threadIdx.x < o) red[threadIdx.x] += red[threadIdx.x + o];
        __syncthreads();
    }
    float inv = 1.f / red[0];
    __syncthreads();

    for (int j = threadIdx.x; j < n; j += 256) {
        float v = srow[j] * inv;
        p[j] = v;
        h[j] = __float2half_rn(v);
    }
    __half z = __float2half_rn(0.f);
    for (int j = n + threadIdx.x; j < band; j += 256) h[j] = z;
    for (int j = n + threadIdx.x; j < S_LEN; j += 256) p[j] = 0.f;
}

// ---------------------------------------------------------------------------
extern "C" void kernel_launch(void* const* d_in, const int* in_sizes, int n_in,
                              void* d_out, int out_size)
{
    (void)in_sizes; (void)n_in; (void)out_size;
    const float* hid  = (const float*)d_in[0];
    const int*   pos  = (const int*)  d_in[1];
    const float* Wqd  = (const float*)d_in[3];
    const float* bqd  = (const float*)d_in[4];
    const float* gq   = (const float*)d_in[5];
    const float* Wqu  = (const float*)d_in[6];
    const float* Wkd  = (const float*)d_in[7];
    const float* bkd  = (const float*)d_in[8];
    const float* gkv  = (const float*)d_in[9];
    const float* Wku  = (const float*)d_in[10];
    const float* Wo   = (const float*)d_in[11];

    float* out  = (float*)d_out;
    float* attn = out + (long)S_LEN * HID;

    void *pf = nullptr, *ph = nullptr;
    cudaGetSymbolAddress(&pf, g_f32);
    cudaGetSymbolAddress(&ph, g_h16);
    float*  F = (float*)pf;
    __half* H = (__half*)ph;

    float* qraw = F + F_QRAW;
    float* qbuf = F + F_QBUF;
    float* kvd  = F + F_KVD;
    float* kv   = F + F_KV;
    float* ctx  = F + F_CTX;

    const int SMEM_NT = STG * 20480;   // 61440
    const int SMEM_TR = STG * 18944;   // 56832
    static bool attr_done = false;
    if (!attr_done) {
        cudaFuncSetAttribute(gemm_h<false,false,false>,
            cudaFuncAttributeMaxDynamicSharedMemorySize, SMEM_NT);
        cudaFuncSetAttribute(gemm_h<true,false,false>,
            cudaFuncAttributeMaxDynamicSharedMemorySize, SMEM_NT);
        cudaFuncSetAttribute(gemm_h<false,true,true>,
            cudaFuncAttributeMaxDynamicSharedMemorySize, SMEM_TR);
        attr_done = true;
    }

    const dim3 blk(256);
    const float qk_scale = 0.07216878364870323f;   // 1/sqrt(192)

    // 0. convert inputs to fp16 (Wkd into 640-row padded region)
    cvt_h<<<(unsigned)(((long)S_LEN*HID+1023)/1024), blk>>>(hid, H+O_HID, (long)S_LEN*HID);
    cvt_h<<<(unsigned)(((long)QLR*HID+1023)/1024), blk>>>(Wqd, H+O_WQD, (long)QLR*HID);
    cvt_h<<<(unsigned)(((long)QUP_N*QLR+1023)/1024), blk>>>(Wqu, H+O_WQU, (long)QUP_N*QLR);
    cvt_h<<<(unsigned)(((long)KVD_W*HID+1023)/1024), blk>>>(Wkd, H+O_WKD, (long)KVD_W*HID);
    cvt_h<<<(unsigned)(((long)KUP_N*KVLR+1023)/1024), blk>>>(Wku, H+O_WKU, (long)KUP_N*KVLR);
    cvt_h<<<(unsigned)(((long)HID*HEADS*VD+1023)/1024), blk>>>(Wo, H+O_WO, (long)HID*HEADS*VD);

    // 1. qraw = hid @ Wq_down^T + bq
    gemm_h<false,false,false><<<dim3(QLR/128, S_LEN/128, 1), blk, SMEM_NT>>>(
        H+O_HID, 0, H+O_WQD, 0, qraw, 0, nullptr,
        HID, HID, HID, QLR, QLR, bqd, 1.f);
    // 2. rmsnorm -> fp16
    rmsnorm_h<<<S_LEN, blk>>>(qraw, gq, H+O_QRN, QLR, QLR);
    // 3. q = qrn @ Wq_up^T
    gemm_h<false,false,false><<<dim3(QUP_N/128, S_LEN/128, 1), blk, SMEM_NT>>>(
        H+O_QRN, 0, H+O_WQU, 0, qbuf, 0, nullptr,
        QLR, QLR, QLR, QUP_N, QUP_N, nullptr, 1.f);
    // 4. kvd = hid @ Wkv_down^T + bkv  (N=576 via 640-padded weights)
    gemm_h<false,false,false><<<dim3(WKD_PAD/128, S_LEN/128, 1), blk, SMEM_NT>>>(
        H+O_HID, 0, H+O_WKD, 0, kvd, 0, nullptr,
        HID, HID, HID, KVD_W, KVD_W, bkd, 1.f);
    // 5. rmsnorm first 512 cols -> fp16
    rmsnorm_h<<<S_LEN, blk>>>(kvd, gkv, H+O_KVN, KVLR, KVD_W);
    // 6. kv = kvn @ Wkv_up^T ; epilogue also emits fp16 kv16 copy for PV
    gemm_h<false,false,false><<<dim3(KUP_N/128, S_LEN/128, 1), blk, SMEM_NT>>>(
        H+O_KVN, 0, H+O_WKU, 0, kv, 0, H+O_KV16,
        KVLR, KVLR, KVLR, KUP_N, KUP_N, nullptr, 1.f);
    // 7. assemble + rope -> fp16 qall/kall
    assemble_rope<<<S_LEN, blk>>>(qbuf, kvd, kv, pos, H+O_QALL, H+O_KALL);
    // 8. scores -> attn fp32 (causal block skip)
    gemm_h<true,false,false><<<dim3(S_LEN/128, S_LEN/128, HEADS), blk, SMEM_NT>>>(
        H+O_QALL, (long)S_LEN*QD, H+O_KALL, (long)S_LEN*QD,
        attn, (long)S_LEN*S_LEN, nullptr,
        QD, QD, QD, S_LEN, S_LEN, nullptr, qk_scale);
    // 9. causal softmax -> fp32 + fp16 (single DRAM read)
    softmax_causal<<<HEADS * S_LEN, blk>>>(attn, H+O_ATTN);
    // 10. ctx = attn @ v (NN gemm, K clamped at diagonal). B = kv16 v-block,
    //     head stride 256 elements within each 4096-wide row.
    gemm_h<false,true,true><<<dim3(1, S_LEN/128, HEADS), blk, SMEM_TR>>>(
        H+O_ATTN, (long)S_LEN*S_LEN,
        H+O_KV16 + NOPE, 256,
        ctx, (long)VD, H+O_CTX,
        S_LEN, S_LEN, KUP_N, HID, VD, nullptr, 1.f);
    // 11. out = ctx @ Wo^T
    gemm_h<false,false,false><<<dim3(HID/128, S_LEN/128, 1), blk, SMEM_NT>>>(
        H+O_CTX, 0, H+O_WO, 0, out, 0, nullptr,
        HID, HID, HID, HID, HID, nullptr, 1.f);
}